// round 8
// baseline (speedup 1.0000x reference)
#include <cuda_runtime.h>
#include <math.h>
#include <stdint.h>

// Problem constants
#define DIM    1024
#define BATCH  1024
#define KSET   128
#define N_MEM  100000

// ---------------- device scratch (no allocations allowed) ----------------
__device__ float g_h[BATCH * DIM];         // hidden after GELU (4 MB)
__device__ float g_q[BATCH * DIM];         // queries (4 MB)

// =========================================================================
// 3xTF32 tensor-core GEMM v2 (NT): C = act(A[M,K] @ B[N,K]^T + bias)
// Changes vs v1 (73us, occ 12.5%, alu 27%):
//  - hi/lo split done ONCE at staging into smem (inner loop = LDS+MMA only)
//  - BM=BN=64 -> grid 256 blocks -> 2 blocks/SM resident (16 warps/SM)
// 8 warps as 2m x 4n, warp tile 32x16 (2x2 m16n8 mma tiles).
// =========================================================================
__device__ __forceinline__ void split_tf32(float x, float& hi, float& lo)
{
    uint32_t h;
    asm("cvt.rna.tf32.f32 %0, %1;" : "=r"(h) : "f"(x));
    hi = __uint_as_float(h);
    float r = x - hi;
    uint32_t l;
    asm("cvt.rna.tf32.f32 %0, %1;" : "=r"(l) : "f"(r));
    lo = __uint_as_float(l);
}

__device__ __forceinline__ void mma_tf32(float* d,
                                         uint32_t a0, uint32_t a1,
                                         uint32_t a2, uint32_t a3,
                                         uint32_t b0, uint32_t b1)
{
    asm volatile(
        "mma.sync.aligned.m16n8k8.row.col.f32.tf32.tf32.f32 "
        "{%0,%1,%2,%3}, {%4,%5,%6,%7}, {%8,%9}, {%0,%1,%2,%3};"
        : "+f"(d[0]), "+f"(d[1]), "+f"(d[2]), "+f"(d[3])
        : "r"(a0), "r"(a1), "r"(a2), "r"(a3), "r"(b0), "r"(b1));
}

__device__ __forceinline__ float gelu_exact(float x) {
    return 0.5f * x * (1.0f + erff(x * 0.70710678118654752f));
}

#define SSTRIDE 72   // 64 + 8 pad: conflict-free staging STS + frag LDS

template<bool USE_GH, bool GELU>
__global__ __launch_bounds__(256, 2)
void gemm_tf32(const float* __restrict__ Ain,
               const float* __restrict__ Bin,
               const float* __restrict__ bias)
{
    const float* A    = USE_GH ? (const float*)g_h : Ain;
    float*       Cout = GELU   ? g_h : g_q;

    const int bm = blockIdx.y * 64;
    const int bn = blockIdx.x * 64;

    // [buf][hilo][k][row]
    __shared__ float s_a[2][2][16][SSTRIDE];
    __shared__ float s_b[2][2][16][SSTRIDE];

    const int tid  = threadIdx.x;
    const int w    = tid >> 5;
    const int lane = tid & 31;
    const int wm   = w & 1;          // m offset wm*32
    const int wn   = w >> 1;         // n offset wn*16
    const int g    = lane >> 2;      // 0..7
    const int tig  = lane & 3;       // 0..3

    // staging: each thread loads one float4 of A and one of B
    const int rowS = tid & 63;       // tile row
    const int sK   = tid >> 6;       // 0..3 -> k offset sK*4

    const float* Ap = A   + (size_t)(bm + rowS) * DIM + sK * 4;
    const float* Bp = Bin + (size_t)(bn + rowS) * DIM + sK * 4;

    float acc[2][2][4];
#pragma unroll
    for (int mt = 0; mt < 2; mt++)
#pragma unroll
        for (int nt = 0; nt < 2; nt++)
#pragma unroll
            for (int i = 0; i < 4; i++) acc[mt][nt][i] = 0.f;

    float4 ra = *(const float4*)(Ap);
    float4 rb = *(const float4*)(Bp);

#define STORE_TILE(BUF)                                                      \
    do {                                                                     \
        float hi, lo;                                                        \
        split_tf32(ra.x, hi, lo);                                            \
        s_a[BUF][0][sK*4+0][rowS] = hi; s_a[BUF][1][sK*4+0][rowS] = lo;      \
        split_tf32(ra.y, hi, lo);                                            \
        s_a[BUF][0][sK*4+1][rowS] = hi; s_a[BUF][1][sK*4+1][rowS] = lo;      \
        split_tf32(ra.z, hi, lo);                                            \
        s_a[BUF][0][sK*4+2][rowS] = hi; s_a[BUF][1][sK*4+2][rowS] = lo;      \
        split_tf32(ra.w, hi, lo);                                            \
        s_a[BUF][0][sK*4+3][rowS] = hi; s_a[BUF][1][sK*4+3][rowS] = lo;      \
        split_tf32(rb.x, hi, lo);                                            \
        s_b[BUF][0][sK*4+0][rowS] = hi; s_b[BUF][1][sK*4+0][rowS] = lo;      \
        split_tf32(rb.y, hi, lo);                                            \
        s_b[BUF][0][sK*4+1][rowS] = hi; s_b[BUF][1][sK*4+1][rowS] = lo;      \
        split_tf32(rb.z, hi, lo);                                            \
        s_b[BUF][0][sK*4+2][rowS] = hi; s_b[BUF][1][sK*4+2][rowS] = lo;      \
        split_tf32(rb.w, hi, lo);                                            \
        s_b[BUF][0][sK*4+3][rowS] = hi; s_b[BUF][1][sK*4+3][rowS] = lo;      \
    } while (0)

    STORE_TILE(0);
    __syncthreads();

    int buf = 0;
#pragma unroll 1
    for (int kt = 0; kt < DIM; kt += 16) {
        const bool more = (kt + 16) < DIM;
        if (more) {
            ra = *(const float4*)(Ap + kt + 16);
            rb = *(const float4*)(Bp + kt + 16);
        }

#pragma unroll
        for (int kk = 0; kk < 16; kk += 8) {
            uint32_t ah[2][4], al[2][4];
#pragma unroll
            for (int mt = 0; mt < 2; mt++) {
                const int m0 = wm * 32 + mt * 16 + g;
                ah[mt][0] = __float_as_uint(s_a[buf][0][kk + tig][m0]);
                ah[mt][1] = __float_as_uint(s_a[buf][0][kk + tig][m0 + 8]);
                ah[mt][2] = __float_as_uint(s_a[buf][0][kk + tig + 4][m0]);
                ah[mt][3] = __float_as_uint(s_a[buf][0][kk + tig + 4][m0 + 8]);
                al[mt][0] = __float_as_uint(s_a[buf][1][kk + tig][m0]);
                al[mt][1] = __float_as_uint(s_a[buf][1][kk + tig][m0 + 8]);
                al[mt][2] = __float_as_uint(s_a[buf][1][kk + tig + 4][m0]);
                al[mt][3] = __float_as_uint(s_a[buf][1][kk + tig + 4][m0 + 8]);
            }
            uint32_t bh[2][2], bl[2][2];
#pragma unroll
            for (int nt = 0; nt < 2; nt++) {
                const int n0 = wn * 16 + nt * 8 + g;
                bh[nt][0] = __float_as_uint(s_b[buf][0][kk + tig][n0]);
                bh[nt][1] = __float_as_uint(s_b[buf][0][kk + tig + 4][n0]);
                bl[nt][0] = __float_as_uint(s_b[buf][1][kk + tig][n0]);
                bl[nt][1] = __float_as_uint(s_b[buf][1][kk + tig + 4][n0]);
            }
#pragma unroll
            for (int nt = 0; nt < 2; nt++)
#pragma unroll
                for (int mt = 0; mt < 2; mt++) {
                    float* d = acc[mt][nt];
                    mma_tf32(d, al[mt][0], al[mt][1], al[mt][2], al[mt][3],
                             bh[nt][0], bh[nt][1]);
                    mma_tf32(d, ah[mt][0], ah[mt][1], ah[mt][2], ah[mt][3],
                             bl[nt][0], bl[nt][1]);
                    mma_tf32(d, ah[mt][0], ah[mt][1], ah[mt][2], ah[mt][3],
                             bh[nt][0], bh[nt][1]);
                }
        }

        if (more) {
            buf ^= 1;
            STORE_TILE(buf);
            __syncthreads();
        }
    }
#undef STORE_TILE

    // fused epilogue: bias (+GELU), write fp32
#pragma unroll
    for (int mt = 0; mt < 2; mt++) {
        const int r0 = bm + wm * 32 + mt * 16 + g;
#pragma unroll
        for (int nt = 0; nt < 2; nt++) {
            const int c0 = bn + wn * 16 + nt * 8 + 2 * tig;
            const float2 bb = *(const float2*)&bias[c0];
            float2 v0, v1;
            v0.x = acc[mt][nt][0] + bb.x;
            v0.y = acc[mt][nt][1] + bb.y;
            v1.x = acc[mt][nt][2] + bb.x;
            v1.y = acc[mt][nt][3] + bb.y;
            if (GELU) {
                v0.x = gelu_exact(v0.x); v0.y = gelu_exact(v0.y);
                v1.x = gelu_exact(v1.x); v1.y = gelu_exact(v1.y);
            }
            *(float2*)&Cout[(size_t)r0 * DIM + c0]       = v0;
            *(float2*)&Cout[(size_t)(r0 + 8) * DIM + c0] = v1;
        }
    }
}

// =========================================================================
// Fused gather + scores + softmax + recombine (single HBM pass per row).
// Measured at ~77us = ~7 TB/s effective -> already at HBM roofline. Unchanged.
// =========================================================================
__global__ __launch_bounds__(256)
void attn_kernel(const float* __restrict__ mem,
                 const int* __restrict__ kset,
                 float* __restrict__ p_out,
                 float* __restrict__ y_out)
{
    const int b    = blockIdx.x;
    const int tid  = threadIdx.x;
    const int w    = tid >> 5;
    const int lane = tid & 31;

    __shared__ float s_scores[KSET];
    __shared__ float s_m[8];
    __shared__ float s_s[8];
    __shared__ float s_y[8][DIM];   // 32 KB

    const float4* qv = (const float4*)(g_q + (size_t)b * DIM);
    float4 qr[8];
#pragma unroll
    for (int j = 0; j < 8; j++) qr[j] = qv[lane + 32 * j];

    float m = -INFINITY, s = 0.f;
    float4 y[8];
#pragma unroll
    for (int j = 0; j < 8; j++) y[j] = make_float4(0.f, 0.f, 0.f, 0.f);

    const int* krow = kset + (size_t)b * KSET;

#pragma unroll 1
    for (int i = 0; i < 16; i++) {
        const int k = w * 16 + i;
        int idx = krow[k];
        idx = min(max(idx, 0), N_MEM - 1);   // defensive clamp
        const float4* rv = (const float4*)(mem + (size_t)idx * DIM);

        float4 r[8];
#pragma unroll
        for (int j = 0; j < 8; j++) r[j] = rv[lane + 32 * j];

        float part = 0.f;
#pragma unroll
        for (int j = 0; j < 8; j++) {
            part = fmaf(r[j].x, qr[j].x, part);
            part = fmaf(r[j].y, qr[j].y, part);
            part = fmaf(r[j].z, qr[j].z, part);
            part = fmaf(r[j].w, qr[j].w, part);
        }
#pragma unroll
        for (int o = 16; o > 0; o >>= 1)
            part += __shfl_xor_sync(0xFFFFFFFFu, part, o);

        if (lane == 0) s_scores[k] = part;

        const float mn    = fmaxf(m, part);
        const float scale = __expf(m - mn);
        const float e     = __expf(part - mn);
        s = s * scale + e;
#pragma unroll
        for (int j = 0; j < 8; j++) {
            y[j].x = fmaf(y[j].x, scale, e * r[j].x);
            y[j].y = fmaf(y[j].y, scale, e * r[j].y);
            y[j].z = fmaf(y[j].z, scale, e * r[j].z);
            y[j].w = fmaf(y[j].w, scale, e * r[j].w);
        }
        m = mn;
    }

    if (lane == 0) { s_m[w] = m; s_s[w] = s; }
    __syncthreads();

    float M = -INFINITY;
#pragma unroll
    for (int w2 = 0; w2 < 8; w2++) M = fmaxf(M, s_m[w2]);
    float S = 0.f;
#pragma unroll
    for (int w2 = 0; w2 < 8; w2++) S += s_s[w2] * __expf(s_m[w2] - M);
    const float invS = 1.f / S;

    const float f = __expf(m - M);
    float4* ys = (float4*)s_y[w];
#pragma unroll
    for (int j = 0; j < 8; j++) {
        float4 v = y[j];
        v.x *= f; v.y *= f; v.z *= f; v.w *= f;
        ys[lane + 32 * j] = v;
    }
    __syncthreads();

    {
        float4 acc = make_float4(0.f, 0.f, 0.f, 0.f);
#pragma unroll
        for (int w2 = 0; w2 < 8; w2++) {
            float4 v = ((const float4*)s_y[w2])[tid];
            acc.x += v.x; acc.y += v.y; acc.z += v.z; acc.w += v.w;
        }
        acc.x *= invS; acc.y *= invS; acc.z *= invS; acc.w *= invS;
        ((float4*)(y_out + (size_t)b * DIM))[tid] = acc;
    }

    if (tid < KSET)
        p_out[(size_t)b * KSET + tid] = __expf(s_scores[tid] - M) * invS;
}

// =========================================================================
// Launch: GEMM1(fused GELU->g_h) -> GEMM2(fused bias->g_q) -> attention
// Output layout: P0 [B,K] flattened first, then Y0 [B,D].
// =========================================================================
extern "C" void kernel_launch(void* const* d_in, const int* in_sizes, int n_in,
                              void* d_out, int out_size)
{
    const float* emb  = (const float*)d_in[0];
    const float* mem  = (const float*)d_in[1];
    const int*   kset = (const int*)d_in[2];
    const float* W1   = (const float*)d_in[3];
    const float* b1   = (const float*)d_in[4];
    const float* W2   = (const float*)d_in[5];
    const float* b2   = (const float*)d_in[6];

    float* out   = (float*)d_out;
    float* p_out = out;                    // [B, K]
    float* y_out = out + BATCH * KSET;     // [B, D]

    dim3 ggrid(16, 16);   // (N/64, M/64) = 256 blocks

    gemm_tf32<false, true ><<<ggrid, 256>>>(emb, W1, b1);
    gemm_tf32<true,  false><<<ggrid, 256>>>(nullptr, W2, b2);
    attn_kernel<<<BATCH, 256>>>(mem, kset, p_out, y_out);
}